// round 2
// baseline (speedup 1.0000x reference)
#include <cuda_runtime.h>
#include <cuda_bf16.h>

// Problem constants (fixed by the dataset)
#define N_NODES 50000
#define E_EDGES 1600000
#define DIM     128
#define D4      32          // DIM / 4 float4s per row

// ---------------------------------------------------------------------------
// Scratch (device globals — no allocation allowed in kernel_launch)
// ---------------------------------------------------------------------------
__device__ float g_h   [N_NODES * DIM];   // h = x @ W
__device__ float g_agg [N_NODES * DIM];   // aggregation buffer
__device__ float g_x1  [N_NODES * DIM];   // layer-1 output (layer-2 input)
__device__ float g_dinv[N_NODES];
__device__ int   g_deg [N_NODES];
__device__ float g_norm[E_EDGES];

// ---------------------------------------------------------------------------
// Degree / normalization
// ---------------------------------------------------------------------------
__global__ void zero_deg_kernel() {
    int i = blockIdx.x * blockDim.x + threadIdx.x;
    if (i < N_NODES) g_deg[i] = 0;
}

__global__ void hist_kernel(const int* __restrict__ dst) {
    int e = blockIdx.x * blockDim.x + threadIdx.x;
    if (e < E_EDGES) atomicAdd(&g_deg[dst[e]], 1);
}

__global__ void dinv_kernel() {
    int i = blockIdx.x * blockDim.x + threadIdx.x;
    if (i < N_NODES) {
        // +1 for the self-loop added by gcn_norm
        g_dinv[i] = rsqrtf((float)(g_deg[i] + 1));
    }
}

__global__ void norm_kernel(const int* __restrict__ src, const int* __restrict__ dst) {
    int e = blockIdx.x * blockDim.x + threadIdx.x;
    if (e < E_EDGES) {
        g_norm[e] = g_dinv[dst[e]] * g_dinv[src[e]];
    }
}

// ---------------------------------------------------------------------------
// GEMM: C[n,128] = A[n,128] @ W[128,128]  (fp32, shared-memory tiled)
// Block: 256 threads, tile = 64 rows x 128 cols, K-chunks of 32.
// Each thread computes 8 rows x 4 cols.
// ---------------------------------------------------------------------------
#define GEMM_BM 64

__global__ __launch_bounds__(256) void gemm_kernel(
    const float* __restrict__ A, const float* __restrict__ W,
    float* __restrict__ C, int n)
{
    __shared__ float xs[GEMM_BM][32];   // [m][k]
    __shared__ float ws[32][DIM];       // [k][col]

    const int tid  = threadIdx.x;
    const int cg   = (tid & 31) * 4;    // col base (32 groups x 4)
    const int mg   = (tid >> 5) * 8;    // row base within tile (8 groups x 8)
    const int row0 = blockIdx.x * GEMM_BM;

    float acc[8][4];
    #pragma unroll
    for (int i = 0; i < 8; i++)
        #pragma unroll
        for (int j = 0; j < 4; j++) acc[i][j] = 0.f;

    for (int kc = 0; kc < DIM; kc += 32) {
        // load x tile: 64*32 = 2048 floats, 8 per thread, coalesced
        #pragma unroll
        for (int i = 0; i < 8; i++) {
            int t = tid + i * 256;
            int m = t >> 5, k = t & 31;
            int row = row0 + m;
            xs[m][k] = (row < n) ? A[(size_t)row * DIM + kc + k] : 0.f;
        }
        // load W tile: 32*128 = 4096 floats, 16 per thread, coalesced
        #pragma unroll
        for (int i = 0; i < 16; i++) {
            int t = tid + i * 256;
            int kk = t >> 7, col = t & 127;
            ws[kk][col] = W[(size_t)(kc + kk) * DIM + col];
        }
        __syncthreads();

        #pragma unroll
        for (int kk = 0; kk < 32; kk++) {
            float4 w4 = *(const float4*)&ws[kk][cg];
            #pragma unroll
            for (int i = 0; i < 8; i++) {
                float a = xs[mg + i][kk];
                acc[i][0] += a * w4.x;
                acc[i][1] += a * w4.y;
                acc[i][2] += a * w4.z;
                acc[i][3] += a * w4.w;
            }
        }
        __syncthreads();
    }

    #pragma unroll
    for (int i = 0; i < 8; i++) {
        int row = row0 + mg + i;
        if (row < n) {
            float4 v = make_float4(acc[i][0], acc[i][1], acc[i][2], acc[i][3]);
            *(float4*)&C[(size_t)row * DIM + cg] = v;
        }
    }
}

// ---------------------------------------------------------------------------
// Self-loop init: agg[i] = h[i] * dinv[i]^2   (also serves as the zero-init)
// ---------------------------------------------------------------------------
__global__ void selfloop_kernel() {
    int idx = blockIdx.x * blockDim.x + threadIdx.x;   // over N*D4 float4s
    if (idx < N_NODES * D4) {
        int node = idx >> 5;
        float s  = g_dinv[node];
        float sc = s * s;
        float4 v = ((const float4*)g_h)[idx];
        v.x *= sc; v.y *= sc; v.z *= sc; v.w *= sc;
        ((float4*)g_agg)[idx] = v;
    }
}

// ---------------------------------------------------------------------------
// Edge scatter: warp per edge. agg[dst] += h[src] * norm  (v4 reductions)
// ---------------------------------------------------------------------------
__global__ __launch_bounds__(256) void scatter_kernel(
    const int* __restrict__ src, const int* __restrict__ dst)
{
    const int lane = threadIdx.x & 31;
    const int gw   = (blockIdx.x * blockDim.x + threadIdx.x) >> 5;
    const int nw   = (gridDim.x * blockDim.x) >> 5;

    for (int e = gw; e < E_EDGES; e += nw) {
        int   s  = src[e];
        int   d  = dst[e];
        float nm = g_norm[e];
        float4 v = *(const float4*)(g_h + (size_t)s * DIM + lane * 4);
        v.x *= nm; v.y *= nm; v.z *= nm; v.w *= nm;
        float* p = g_agg + (size_t)d * DIM + lane * 4;
        asm volatile("red.global.add.v4.f32 [%0], {%1, %2, %3, %4};"
                     :: "l"(p), "f"(v.x), "f"(v.y), "f"(v.z), "f"(v.w)
                     : "memory");
    }
}

// ---------------------------------------------------------------------------
// out = relu(agg + b)
// ---------------------------------------------------------------------------
__global__ void bias_relu_kernel(const float* __restrict__ b, float* __restrict__ out) {
    int idx = blockIdx.x * blockDim.x + threadIdx.x;   // over N*D4 float4s
    if (idx < N_NODES * D4) {
        int c = idx & 31;
        float4 b4 = ((const float4*)b)[c];
        float4 v  = ((const float4*)g_agg)[idx];
        v.x = fmaxf(v.x + b4.x, 0.f);
        v.y = fmaxf(v.y + b4.y, 0.f);
        v.z = fmaxf(v.z + b4.z, 0.f);
        v.w = fmaxf(v.w + b4.w, 0.f);
        ((float4*)out)[idx] = v;
    }
}

// ---------------------------------------------------------------------------
// Launch
// ---------------------------------------------------------------------------
extern "C" void kernel_launch(void* const* d_in, const int* in_sizes, int n_in,
                              void* d_out, int out_size)
{
    const float* x   = (const float*)d_in[0];
    const int*   ei  = (const int*)  d_in[1];   // [2, E]: row0 = src, row1 = dst
    const float* W0  = (const float*)d_in[2];
    const float* b0  = (const float*)d_in[3];
    const float* W1  = (const float*)d_in[4];
    const float* b1  = (const float*)d_in[5];
    float*       out = (float*)d_out;

    const int* src = ei;
    const int* dst = ei + E_EDGES;

    float *h_ptr, *x1_ptr;
    cudaGetSymbolAddress((void**)&h_ptr,  g_h);
    cudaGetSymbolAddress((void**)&x1_ptr, g_x1);

    const int TB = 256;
    const int gridN  = (N_NODES + TB - 1) / TB;
    const int gridE  = (E_EDGES + TB - 1) / TB;
    const int gridND = (N_NODES * D4 + TB - 1) / TB;
    const int gridG  = (N_NODES + GEMM_BM - 1) / GEMM_BM;
    const int gridS  = 2048;   // persistent-ish warp grid for the scatter

    // --- normalization precompute ---
    zero_deg_kernel<<<gridN, TB>>>();
    hist_kernel<<<gridE, TB>>>(dst);
    dinv_kernel<<<gridN, TB>>>();
    norm_kernel<<<gridE, TB>>>(src, dst);

    // --- layer 1 ---
    gemm_kernel<<<gridG, TB>>>(x, W0, h_ptr, N_NODES);
    selfloop_kernel<<<gridND, TB>>>();
    scatter_kernel<<<gridS, TB>>>(src, dst);
    bias_relu_kernel<<<gridND, TB>>>(b0, x1_ptr);

    // --- layer 2 ---
    gemm_kernel<<<gridG, TB>>>(x1_ptr, W1, h_ptr, N_NODES);
    selfloop_kernel<<<gridND, TB>>>();
    scatter_kernel<<<gridS, TB>>>(src, dst);
    bias_relu_kernel<<<gridND, TB>>>(b1, out);
}

// round 3
// speedup vs baseline: 1.4282x; 1.4282x over previous
#include <cuda_runtime.h>
#include <cuda_bf16.h>

#define N_NODES 50000
#define E_EDGES 1600000
#define DIM     128

// ---------------------------------------------------------------------------
// Scratch (device globals — no allocation allowed)
// ---------------------------------------------------------------------------
__device__ float g_h   [N_NODES * DIM];   // h = x @ W
__device__ float g_x1  [N_NODES * DIM];   // layer-1 output
__device__ float g_dinv[N_NODES];
__device__ int   g_deg [N_NODES];
__device__ int   g_off [N_NODES + 1];     // CSR row offsets (by dst)
__device__ int   g_cur [N_NODES];         // insertion cursors
__device__ int2  g_edge[E_EDGES];         // {src, __float_as_int(norm)} sorted by dst

// ---------------------------------------------------------------------------
// Degree histogram
// ---------------------------------------------------------------------------
__global__ void zero_deg_kernel() {
    int i = blockIdx.x * blockDim.x + threadIdx.x;
    if (i < N_NODES) g_deg[i] = 0;
}

__global__ void hist_kernel(const int* __restrict__ dst) {
    int e = blockIdx.x * blockDim.x + threadIdx.x;
    if (e < E_EDGES) atomicAdd(&g_deg[dst[e]], 1);
}

// ---------------------------------------------------------------------------
// Single-block scan: exclusive prefix of deg -> g_off, g_cur; dinv = rsqrt(deg+1)
// ---------------------------------------------------------------------------
__global__ __launch_bounds__(1024) void scan_kernel() {
    __shared__ int sp[1024];
    const int T = 1024;
    const int tid = threadIdx.x;
    const int chunk = (N_NODES + T - 1) / T;     // 49
    const int lo = tid * chunk;
    const int hi = min(lo + chunk, N_NODES);

    int s = 0;
    for (int i = lo; i < hi; i++) s += g_deg[i];
    sp[tid] = s;
    __syncthreads();

    // Hillis-Steele inclusive scan
    for (int off = 1; off < T; off <<= 1) {
        int v = (tid >= off) ? sp[tid - off] : 0;
        __syncthreads();
        sp[tid] += v;
        __syncthreads();
    }

    int base = (tid > 0) ? sp[tid - 1] : 0;      // exclusive prefix
    for (int i = lo; i < hi; i++) {
        g_off[i] = base;
        g_cur[i] = base;
        g_dinv[i] = rsqrtf((float)(g_deg[i] + 1));   // +1 for self-loop
        base += g_deg[i];
    }
    if (tid == 0) g_off[N_NODES] = E_EDGES;
}

// ---------------------------------------------------------------------------
// Reorder edges into dst-sorted CSR; store {src, norm} packed
// ---------------------------------------------------------------------------
__global__ void reorder_kernel(const int* __restrict__ src, const int* __restrict__ dst) {
    int e = blockIdx.x * blockDim.x + threadIdx.x;
    if (e < E_EDGES) {
        int d = dst[e];
        int s = src[e];
        int p = atomicAdd(&g_cur[d], 1);
        float nm = g_dinv[d] * g_dinv[s];
        g_edge[p] = make_int2(s, __float_as_int(nm));
    }
}

// ---------------------------------------------------------------------------
// GEMM: C[n,128] = A[n,128] @ W[128,128]  using packed fma.rn.f32x2 (2 FMA/op)
// Block 256 threads, tile 128x128, K-chunks of 32. Thread: 8 rows (4 pairs) x 8 cols.
// ---------------------------------------------------------------------------
#define BM 128
#define BN 128
#define BK 32
#define BMP (BM + 4)   // padded row to kill smem store bank conflicts

typedef unsigned long long ull;

__device__ __forceinline__ void ffma2(ull& d, ull a, ull b) {
    asm("fma.rn.f32x2 %0, %1, %2, %0;" : "+l"(d) : "l"(a), "l"(b));
}

__global__ __launch_bounds__(256) void gemm_kernel(
    const float* __restrict__ A, const float* __restrict__ W,
    float* __restrict__ C, int n)
{
    __shared__ float xsf[BK][BMP];        // [k][m]  (pairs of rows read as 8B)
    __shared__ float2 ws2[BK][BN];        // {w, w} duplicated

    const int tid  = threadIdx.x;
    const int c0   = tid & 15;            // col base; cols = c0 + j*16
    const int mp   = (tid >> 4) * 4;      // row-pair base (4 pairs = 8 rows)
    const int row0 = blockIdx.x * BM;

    ull acc[4][8];
    #pragma unroll
    for (int p = 0; p < 4; p++)
        #pragma unroll
        for (int j = 0; j < 8; j++) acc[p][j] = 0ull;

    for (int kc = 0; kc < DIM; kc += BK) {
        // A tile: 128x32, 16 floats/thread, coalesced over k
        #pragma unroll
        for (int i = 0; i < 16; i++) {
            int t = tid + i * 256;
            int k = t & 31, m = t >> 5;
            int row = row0 + m;
            xsf[k][m] = (row < n) ? A[(size_t)row * DIM + kc + k] : 0.f;
        }
        // W tile duplicated: 32x128 values, 16/thread, coalesced over col
        #pragma unroll
        for (int i = 0; i < 16; i++) {
            int t = tid + i * 256;
            int k = t >> 7, col = t & 127;
            float w = W[(size_t)(kc + k) * DIM + col];
            ws2[k][col] = make_float2(w, w);
        }
        __syncthreads();

        #pragma unroll
        for (int kk = 0; kk < BK; kk++) {
            ull a[4];
            #pragma unroll
            for (int p = 0; p < 4; p++)
                a[p] = *reinterpret_cast<const ull*>(&xsf[kk][(mp + p) * 2]);
            ull w[8];
            #pragma unroll
            for (int j = 0; j < 8; j++)
                w[j] = *reinterpret_cast<const ull*>(&ws2[kk][c0 + j * 16]);
            #pragma unroll
            for (int p = 0; p < 4; p++)
                #pragma unroll
                for (int j = 0; j < 8; j++)
                    ffma2(acc[p][j], a[p], w[j]);
        }
        __syncthreads();
    }

    #pragma unroll
    for (int p = 0; p < 4; p++) {
        int r0 = row0 + (mp + p) * 2;
        if (r0 < n) {
            #pragma unroll
            for (int j = 0; j < 8; j++)
                C[(size_t)r0 * DIM + c0 + j * 16] =
                    __uint_as_float((unsigned)(acc[p][j] & 0xffffffffull));
        }
        if (r0 + 1 < n) {
            #pragma unroll
            for (int j = 0; j < 8; j++)
                C[(size_t)(r0 + 1) * DIM + c0 + j * 16] =
                    __uint_as_float((unsigned)(acc[p][j] >> 32));
        }
    }
}

// ---------------------------------------------------------------------------
// Fused aggregate: warp per node.
// out[d] = relu( h[d]*dinv[d]^2 + sum_e h[src_e]*norm_e + b )
// Edge list is dst-sorted CSR -> sequential coalesced edge reads, no atomics,
// single coalesced output write.
// ---------------------------------------------------------------------------
__global__ __launch_bounds__(256) void aggregate_kernel(
    const float* __restrict__ h, const float* __restrict__ b,
    float* __restrict__ out)
{
    const int lane = threadIdx.x & 31;
    const int node = (blockIdx.x * blockDim.x + threadIdx.x) >> 5;  // exact: 6250*8 = 50000
    if (node >= N_NODES) return;

    const int beg = g_off[node];
    const int end = g_off[node + 1];
    const float dv = g_dinv[node];
    const float sc = dv * dv;

    float4 acc = *(const float4*)(h + (size_t)node * DIM + lane * 4);
    acc.x *= sc; acc.y *= sc; acc.z *= sc; acc.w *= sc;

    int e = beg;
    for (; e + 2 <= end; e += 2) {
        int2 e0 = g_edge[e];
        int2 e1 = g_edge[e + 1];
        float n0 = __int_as_float(e0.y);
        float n1 = __int_as_float(e1.y);
        float4 v0 = *(const float4*)(h + (size_t)e0.x * DIM + lane * 4);
        float4 v1 = *(const float4*)(h + (size_t)e1.x * DIM + lane * 4);
        acc.x += v0.x * n0; acc.y += v0.y * n0; acc.z += v0.z * n0; acc.w += v0.w * n0;
        acc.x += v1.x * n1; acc.y += v1.y * n1; acc.z += v1.z * n1; acc.w += v1.w * n1;
    }
    if (e < end) {
        int2 e0 = g_edge[e];
        float n0 = __int_as_float(e0.y);
        float4 v0 = *(const float4*)(h + (size_t)e0.x * DIM + lane * 4);
        acc.x += v0.x * n0; acc.y += v0.y * n0; acc.z += v0.z * n0; acc.w += v0.w * n0;
    }

    float4 b4 = *(const float4*)(b + lane * 4);
    acc.x = fmaxf(acc.x + b4.x, 0.f);
    acc.y = fmaxf(acc.y + b4.y, 0.f);
    acc.z = fmaxf(acc.z + b4.z, 0.f);
    acc.w = fmaxf(acc.w + b4.w, 0.f);
    *(float4*)(out + (size_t)node * DIM + lane * 4) = acc;
}

// ---------------------------------------------------------------------------
// Launch
// ---------------------------------------------------------------------------
extern "C" void kernel_launch(void* const* d_in, const int* in_sizes, int n_in,
                              void* d_out, int out_size)
{
    const float* x   = (const float*)d_in[0];
    const int*   ei  = (const int*)  d_in[1];
    const float* W0  = (const float*)d_in[2];
    const float* b0  = (const float*)d_in[3];
    const float* W1  = (const float*)d_in[4];
    const float* b1  = (const float*)d_in[5];
    float*       out = (float*)d_out;

    const int* src = ei;
    const int* dst = ei + E_EDGES;

    float *h_ptr, *x1_ptr;
    cudaGetSymbolAddress((void**)&h_ptr,  g_h);
    cudaGetSymbolAddress((void**)&x1_ptr, g_x1);

    const int TB = 256;
    const int gridN = (N_NODES + TB - 1) / TB;
    const int gridE = (E_EDGES + TB - 1) / TB;
    const int gridG = (N_NODES + BM - 1) / BM;
    const int gridA = (N_NODES * 32 + TB - 1) / TB;   // warp per node

    // CSR + normalization precompute (once, reused by both layers)
    zero_deg_kernel<<<gridN, TB>>>();
    hist_kernel<<<gridE, TB>>>(dst);
    scan_kernel<<<1, 1024>>>();
    reorder_kernel<<<gridE, TB>>>(src, dst);

    // layer 1
    gemm_kernel<<<gridG, TB>>>(x, W0, h_ptr, N_NODES);
    aggregate_kernel<<<gridA, TB>>>(h_ptr, b0, x1_ptr);

    // layer 2
    gemm_kernel<<<gridG, TB>>>(x1_ptr, W1, h_ptr, N_NODES);
    aggregate_kernel<<<gridA, TB>>>(h_ptr, b1, out);
}

// round 4
// speedup vs baseline: 1.4344x; 1.0043x over previous
#include <cuda_runtime.h>
#include <cuda_bf16.h>

#define N_NODES 50000
#define E_EDGES 1600000
#define DIM     128

// ---------------------------------------------------------------------------
// Scratch (device globals — no allocation allowed)
// ---------------------------------------------------------------------------
__device__ float g_h   [N_NODES * DIM];   // h = x @ W
__device__ float g_x1  [N_NODES * DIM];   // layer-1 output
__device__ float g_dinv[N_NODES];
__device__ int   g_deg [N_NODES];
__device__ int   g_off [N_NODES + 1];     // CSR row offsets (by dst)
__device__ int   g_cur [N_NODES];         // insertion cursors
__device__ int2  g_edge[E_EDGES];         // {src, __float_as_int(norm)} sorted by dst

// ---------------------------------------------------------------------------
// Degree histogram
// ---------------------------------------------------------------------------
__global__ void zero_deg_kernel() {
    int i = blockIdx.x * blockDim.x + threadIdx.x;
    if (i < N_NODES) g_deg[i] = 0;
}

__global__ void hist_kernel(const int* __restrict__ dst) {
    int e = blockIdx.x * blockDim.x + threadIdx.x;
    if (e < E_EDGES) atomicAdd(&g_deg[dst[e]], 1);
}

// ---------------------------------------------------------------------------
// Single-block scan: exclusive prefix of deg -> g_off, g_cur; dinv = rsqrt(deg+1)
// ---------------------------------------------------------------------------
__global__ __launch_bounds__(1024) void scan_kernel() {
    __shared__ int sp[1024];
    const int T = 1024;
    const int tid = threadIdx.x;
    const int chunk = (N_NODES + T - 1) / T;     // 49
    const int lo = tid * chunk;
    const int hi = min(lo + chunk, N_NODES);

    int s = 0;
    for (int i = lo; i < hi; i++) s += g_deg[i];
    sp[tid] = s;
    __syncthreads();

    // Hillis-Steele inclusive scan
    for (int off = 1; off < T; off <<= 1) {
        int v = (tid >= off) ? sp[tid - off] : 0;
        __syncthreads();
        sp[tid] += v;
        __syncthreads();
    }

    int base = (tid > 0) ? sp[tid - 1] : 0;      // exclusive prefix
    for (int i = lo; i < hi; i++) {
        g_off[i] = base;
        g_cur[i] = base;
        g_dinv[i] = rsqrtf((float)(g_deg[i] + 1));   // +1 for self-loop
        base += g_deg[i];
    }
    if (tid == 0) g_off[N_NODES] = E_EDGES;
}

// ---------------------------------------------------------------------------
// Reorder edges into dst-sorted CSR; store {src, norm} packed
// ---------------------------------------------------------------------------
__global__ void reorder_kernel(const int* __restrict__ src, const int* __restrict__ dst) {
    int e = blockIdx.x * blockDim.x + threadIdx.x;
    if (e < E_EDGES) {
        int d = dst[e];
        int s = src[e];
        int p = atomicAdd(&g_cur[d], 1);
        float nm = g_dinv[d] * g_dinv[s];
        g_edge[p] = make_int2(s, __float_as_int(nm));
    }
}

// ---------------------------------------------------------------------------
// GEMM: C[n,128] = A[n,128] @ W[128,128]  using packed fma.rn.f32x2 (2 FMA/op)
// Block 256 threads, tile 128x128, K-chunks of 32. Thread: 8 rows (4 pairs) x 8 cols.
// ---------------------------------------------------------------------------
#define BM 128
#define BN 128
#define BK 32
#define BMP (BM + 4)   // padded row to kill smem store bank conflicts

typedef unsigned long long ull;

__device__ __forceinline__ void ffma2(ull& d, ull a, ull b) {
    asm("fma.rn.f32x2 %0, %1, %2, %0;" : "+l"(d) : "l"(a), "l"(b));
}

__global__ __launch_bounds__(256) void gemm_kernel(
    const float* __restrict__ A, const float* __restrict__ W,
    float* __restrict__ C, int n)
{
    __shared__ float xsf[BK][BMP];        // [k][m]  (pairs of rows read as 8B)
    __shared__ float2 ws2[BK][BN];        // {w, w} duplicated

    const int tid  = threadIdx.x;
    const int c0   = tid & 15;            // col base; cols = c0 + j*16
    const int mp   = (tid >> 4) * 4;      // row-pair base (4 pairs = 8 rows)
    const int row0 = blockIdx.x * BM;

    ull acc[4][8];
    #pragma unroll
    for (int p = 0; p < 4; p++)
        #pragma unroll
        for (int j = 0; j < 8; j++) acc[p][j] = 0ull;

    for (int kc = 0; kc < DIM; kc += BK) {
        // A tile: 128x32, 16 floats/thread, coalesced over k
        #pragma unroll
        for (int i = 0; i < 16; i++) {
            int t = tid + i * 256;
            int k = t & 31, m = t >> 5;
            int row = row0 + m;
            xsf[k][m] = (row < n) ? A[(size_t)row * DIM + kc + k] : 0.f;
        }
        // W tile duplicated: 32x128 values, 16/thread, coalesced over col
        #pragma unroll
        for (int i = 0; i < 16; i++) {
            int t = tid + i * 256;
            int k = t >> 7, col = t & 127;
            float w = W[(size_t)(kc + k) * DIM + col];
            ws2[k][col] = make_float2(w, w);
        }
        __syncthreads();

        #pragma unroll
        for (int kk = 0; kk < BK; kk++) {
            ull a[4];
            #pragma unroll
            for (int p = 0; p < 4; p++)
                a[p] = *reinterpret_cast<const ull*>(&xsf[kk][(mp + p) * 2]);
            ull w[8];
            #pragma unroll
            for (int j = 0; j < 8; j++)
                w[j] = *reinterpret_cast<const ull*>(&ws2[kk][c0 + j * 16]);
            #pragma unroll
            for (int p = 0; p < 4; p++)
                #pragma unroll
                for (int j = 0; j < 8; j++)
                    ffma2(acc[p][j], a[p], w[j]);
        }
        __syncthreads();
    }

    #pragma unroll
    for (int p = 0; p < 4; p++) {
        int r0 = row0 + (mp + p) * 2;
        if (r0 < n) {
            #pragma unroll
            for (int j = 0; j < 8; j++)
                C[(size_t)r0 * DIM + c0 + j * 16] =
                    __uint_as_float((unsigned)(acc[p][j] & 0xffffffffull));
        }
        if (r0 + 1 < n) {
            #pragma unroll
            for (int j = 0; j < 8; j++)
                C[(size_t)(r0 + 1) * DIM + c0 + j * 16] =
                    __uint_as_float((unsigned)(acc[p][j] >> 32));
        }
    }
}

// ---------------------------------------------------------------------------
// Fused aggregate: warp per node.
// out[d] = relu( h[d]*dinv[d]^2 + sum_e h[src_e]*norm_e + b )
// Edge list is dst-sorted CSR -> sequential coalesced edge reads, no atomics,
// single coalesced output write.
// ---------------------------------------------------------------------------
__global__ __launch_bounds__(256) void aggregate_kernel(
    const float* __restrict__ h, const float* __restrict__ b,
    float* __restrict__ out)
{
    const int lane = threadIdx.x & 31;
    const int node = (blockIdx.x * blockDim.x + threadIdx.x) >> 5;  // exact: 6250*8 = 50000
    if (node >= N_NODES) return;

    const int beg = g_off[node];
    const int end = g_off[node + 1];
    const float dv = g_dinv[node];
    const float sc = dv * dv;

    float4 acc = *(const float4*)(h + (size_t)node * DIM + lane * 4);
    acc.x *= sc; acc.y *= sc; acc.z *= sc; acc.w *= sc;

    int e = beg;
    for (; e + 2 <= end; e += 2) {
        int2 e0 = g_edge[e];
        int2 e1 = g_edge[e + 1];
        float n0 = __int_as_float(e0.y);
        float n1 = __int_as_float(e1.y);
        float4 v0 = *(const float4*)(h + (size_t)e0.x * DIM + lane * 4);
        float4 v1 = *(const float4*)(h + (size_t)e1.x * DIM + lane * 4);
        acc.x += v0.x * n0; acc.y += v0.y * n0; acc.z += v0.z * n0; acc.w += v0.w * n0;
        acc.x += v1.x * n1; acc.y += v1.y * n1; acc.z += v1.z * n1; acc.w += v1.w * n1;
    }
    if (e < end) {
        int2 e0 = g_edge[e];
        float n0 = __int_as_float(e0.y);
        float4 v0 = *(const float4*)(h + (size_t)e0.x * DIM + lane * 4);
        acc.x += v0.x * n0; acc.y += v0.y * n0; acc.z += v0.z * n0; acc.w += v0.w * n0;
    }

    float4 b4 = *(const float4*)(b + lane * 4);
    acc.x = fmaxf(acc.x + b4.x, 0.f);
    acc.y = fmaxf(acc.y + b4.y, 0.f);
    acc.z = fmaxf(acc.z + b4.z, 0.f);
    acc.w = fmaxf(acc.w + b4.w, 0.f);
    *(float4*)(out + (size_t)node * DIM + lane * 4) = acc;
}

// ---------------------------------------------------------------------------
// Launch
// ---------------------------------------------------------------------------
extern "C" void kernel_launch(void* const* d_in, const int* in_sizes, int n_in,
                              void* d_out, int out_size)
{
    const float* x   = (const float*)d_in[0];
    const int*   ei  = (const int*)  d_in[1];
    const float* W0  = (const float*)d_in[2];
    const float* b0  = (const float*)d_in[3];
    const float* W1  = (const float*)d_in[4];
    const float* b1  = (const float*)d_in[5];
    float*       out = (float*)d_out;

    const int* src = ei;
    const int* dst = ei + E_EDGES;

    float *h_ptr, *x1_ptr;
    cudaGetSymbolAddress((void**)&h_ptr,  g_h);
    cudaGetSymbolAddress((void**)&x1_ptr, g_x1);

    const int TB = 256;
    const int gridN = (N_NODES + TB - 1) / TB;
    const int gridE = (E_EDGES + TB - 1) / TB;
    const int gridG = (N_NODES + BM - 1) / BM;
    const int gridA = (N_NODES * 32 + TB - 1) / TB;   // warp per node

    // CSR + normalization precompute (once, reused by both layers)
    zero_deg_kernel<<<gridN, TB>>>();
    hist_kernel<<<gridE, TB>>>(dst);
    scan_kernel<<<1, 1024>>>();
    reorder_kernel<<<gridE, TB>>>(src, dst);

    // layer 1
    gemm_kernel<<<gridG, TB>>>(x, W0, h_ptr, N_NODES);
    aggregate_kernel<<<gridA, TB>>>(h_ptr, b0, x1_ptr);

    // layer 2
    gemm_kernel<<<gridG, TB>>>(x1_ptr, W1, h_ptr, N_NODES);
    aggregate_kernel<<<gridA, TB>>>(h_ptr, b1, out);
}